// round 1
// baseline (speedup 1.0000x reference)
#include <cuda_runtime.h>

// Problem dims (fixed by setup_inputs)
#define BB   8
#define HH   1024
#define WW   1024
#define TS   32      // output tile (TS x TS)
#define HALO 4       // 9x9 window -> +-4
#define RG   40      // TS + 2*HALO
#define NT   256     // threads per block

// accumulators: [0]=cc sum, [1]=dx sum, [2]=dy sum
__device__ double g_acc[3];

__global__ void zero_acc_kernel() {
    g_acc[0] = 0.0; g_acc[1] = 0.0; g_acc[2] = 0.0;
}

__global__ __launch_bounds__(NT) void ncc_kernel(const float* __restrict__ I,
                                                 const float* __restrict__ J)
{
    __shared__ float sI[RG][RG];
    __shared__ float sJ[RG][RG];
    __shared__ float sV[5][TS][RG];   // vertical 9-row sums per quantity
    __shared__ float red[NT / 32];

    const int b   = blockIdx.z;
    const int ty0 = blockIdx.y * TS;
    const int tx0 = blockIdx.x * TS;
    const float* Ib = I + (size_t)b * HH * WW;
    const float* Jb = J + (size_t)b * HH * WW;
    const int tid = threadIdx.x;

    // ---- load region (with zero padding at image borders) ----
    #pragma unroll
    for (int i = tid; i < RG * RG; i += NT) {
        int r = i / RG, c = i - r * RG;
        int gy = ty0 + r - HALO;
        int gx = tx0 + c - HALO;
        float vi = 0.f, vj = 0.f;
        if ((unsigned)gy < (unsigned)HH && (unsigned)gx < (unsigned)WW) {
            vi = Ib[gy * WW + gx];
            vj = Jb[gy * WW + gx];
        }
        sI[r][c] = vi;
        sJ[r][c] = vj;
    }
    __syncthreads();

    // ---- vertical pass: sliding 9-row sums ----
    // 160 tasks: col in [0,40), row-group of 8 output rows
    if (tid < 4 * RG) {
        const int col = tid % RG;
        const int r0  = (tid / RG) * 8;  // first output row of this group
        float aI = 0.f, aJ = 0.f, aI2 = 0.f, aJ2 = 0.f, aIJ = 0.f;
        #pragma unroll
        for (int k = 0; k < 9; k++) {
            float i = sI[r0 + k][col];
            float j = sJ[r0 + k][col];
            aI += i; aJ += j;
            aI2 = fmaf(i, i, aI2);
            aJ2 = fmaf(j, j, aJ2);
            aIJ = fmaf(i, j, aIJ);
        }
        sV[0][r0][col] = aI;  sV[1][r0][col] = aJ;
        sV[2][r0][col] = aI2; sV[3][r0][col] = aJ2; sV[4][r0][col] = aIJ;
        #pragma unroll
        for (int o = 1; o < 8; o++) {
            int y = r0 + o;
            float iN = sI[y + 8][col], jN = sJ[y + 8][col];
            float iO = sI[y - 1][col], jO = sJ[y - 1][col];
            aI  += iN - iO;
            aJ  += jN - jO;
            aI2 += iN * iN - iO * iO;
            aJ2 += jN * jN - jO * jO;
            aIJ += iN * jN - iO * jO;
            sV[0][y][col] = aI;  sV[1][y][col] = aJ;
            sV[2][y][col] = aI2; sV[3][y][col] = aJ2; sV[4][y][col] = aIJ;
        }
    }
    __syncthreads();

    // ---- horizontal pass: each thread does 4 consecutive output columns ----
    const int r  = tid >> 3;         // output row 0..31
    const int c0 = (tid & 7) * 4;    // first output column

    float wI = 0.f, wJ = 0.f, wI2 = 0.f, wJ2 = 0.f, wIJ = 0.f;
    #pragma unroll
    for (int k = 0; k < 9; k++) {
        wI  += sV[0][r][c0 + k];
        wJ  += sV[1][r][c0 + k];
        wI2 += sV[2][r][c0 + k];
        wJ2 += sV[3][r][c0 + k];
        wIJ += sV[4][r][c0 + k];
    }

    const float inv81 = 1.0f / 81.0f;
    float ccSum = 0.f;
    #pragma unroll
    for (int o = 0; o < 4; o++) {
        if (o > 0) {
            wI  += sV[0][r][c0 + 8 + o] - sV[0][r][c0 + o - 1];
            wJ  += sV[1][r][c0 + 8 + o] - sV[1][r][c0 + o - 1];
            wI2 += sV[2][r][c0 + 8 + o] - sV[2][r][c0 + o - 1];
            wJ2 += sV[3][r][c0 + 8 + o] - sV[3][r][c0 + o - 1];
            wIJ += sV[4][r][c0 + 8 + o] - sV[4][r][c0 + o - 1];
        }
        float cross = wIJ - wI * wJ * inv81;
        float Ivar  = wI2 - wI * wI * inv81;
        float Jvar  = wJ2 - wJ * wJ * inv81;
        float cc    = (cross * cross) / (Ivar * Jvar + 1e-9f);
        ccSum += cc;
    }

    // ---- block reduction -> double atomic ----
    #pragma unroll
    for (int off = 16; off; off >>= 1)
        ccSum += __shfl_down_sync(0xffffffffu, ccSum, off);
    if ((tid & 31) == 0) red[tid >> 5] = ccSum;
    __syncthreads();
    if (tid < NT / 32) {
        float v = red[tid];
        #pragma unroll
        for (int off = (NT / 64); off; off >>= 1)
            v += __shfl_down_sync(0xffu, v, off);
        if (tid == 0) atomicAdd(&g_acc[0], (double)v);
    }
}

__global__ __launch_bounds__(NT) void smooth_kernel(const float* __restrict__ s)
{
    __shared__ float redx[NT / 32];
    __shared__ float redy[NT / 32];

    const long NV = (long)BB * 2 * HH * WW / 4;   // float4 elements
    long idx4 = (long)blockIdx.x * NT + threadIdx.x;

    float dx = 0.f, dy = 0.f;
    if (idx4 < NV) {
        long base = idx4 * 4;
        int x  = (int)(base & (WW - 1));          // WW = 1024
        int yy = (int)((base >> 10) & (HH - 1));  // base / WW % HH
        float4 cur = *(const float4*)(s + base);
        float d1 = cur.y - cur.x;
        float d2 = cur.z - cur.y;
        float d3 = cur.w - cur.z;
        dx = d1 * d1 + d2 * d2 + d3 * d3;
        if (x + 4 < WW) {
            float nx = s[base + 4];
            float d4 = nx - cur.w;
            dx += d4 * d4;
        }
        if (yy + 1 < HH) {
            float4 dn = *(const float4*)(s + base + WW);
            float e1 = dn.x - cur.x;
            float e2 = dn.y - cur.y;
            float e3 = dn.z - cur.z;
            float e4 = dn.w - cur.w;
            dy = e1 * e1 + e2 * e2 + e3 * e3 + e4 * e4;
        }
    }

    const int tid = threadIdx.x;
    #pragma unroll
    for (int off = 16; off; off >>= 1) {
        dx += __shfl_down_sync(0xffffffffu, dx, off);
        dy += __shfl_down_sync(0xffffffffu, dy, off);
    }
    if ((tid & 31) == 0) { redx[tid >> 5] = dx; redy[tid >> 5] = dy; }
    __syncthreads();
    if (tid < NT / 32) {
        float vx = redx[tid];
        float vy = redy[tid];
        #pragma unroll
        for (int off = (NT / 64); off; off >>= 1) {
            vx += __shfl_down_sync(0xffu, vx, off);
            vy += __shfl_down_sync(0xffu, vy, off);
        }
        if (tid == 0) {
            atomicAdd(&g_acc[1], (double)vx);
            atomicAdd(&g_acc[2], (double)vy);
        }
    }
}

__global__ void finalize_kernel(float* __restrict__ out)
{
    double nccl = -g_acc[0] / ((double)BB * HH * WW);
    double mdx  =  g_acc[1] / ((double)BB * 2 * HH * (WW - 1));
    double mdy  =  g_acc[2] / ((double)BB * 2 * (HH - 1) * WW);
    double smooth = (mdx + mdy) * 0.5 * 0.01;
    out[0] = (float)(nccl + smooth);
    out[1] = (float)nccl;
    out[2] = (float)smooth;
}

extern "C" void kernel_launch(void* const* d_in, const int* in_sizes, int n_in,
                              void* d_out, int out_size)
{
    const float* I = (const float*)d_in[0];
    const float* J = (const float*)d_in[1];
    const float* s = (const float*)d_in[2];
    // d_in[3] = sum_filt: all-ones 9x9 box filter, baked into the math.
    float* out = (float*)d_out;

    zero_acc_kernel<<<1, 1>>>();

    dim3 grid(WW / TS, HH / TS, BB);
    ncc_kernel<<<grid, NT>>>(I, J);

    long NV = (long)BB * 2 * HH * WW / 4;
    int nblk = (int)((NV + NT - 1) / NT);
    smooth_kernel<<<nblk, NT>>>(s);

    finalize_kernel<<<1, 1>>>(out);
}

// round 2
// speedup vs baseline: 1.0713x; 1.0713x over previous
#include <cuda_runtime.h>

#define BB 8
#define HH 1024
#define WW 1024
#define TSX 32
#define TSY 64
#define RGX 40            // TSX + 8
#define RGY 72            // TSY + 8
#define SX  41            // padded smem stride (odd -> conflict-free)
#define NT  256

#define NCC_BX (WW / TSX)                 // 32
#define NCC_BY (HH / TSY)                 // 16
#define NCC_BLOCKS (NCC_BX * NCC_BY * BB) // 4096
#define SM_R 64
#define SM_STRIPS (HH / SM_R)             // 16
#define SM_PLANES (BB * 2)                // 16
#define SM_BLOCKS (SM_PLANES * SM_STRIPS) // 256
#define TOTAL_BLOCKS (SM_BLOCKS + NCC_BLOCKS)

#define SMEM_FLOATS (2 * RGY * SX + 5 * TSY * SX)   // 19024 floats = 76096 B

__device__ double g_acc[3] = {0.0, 0.0, 0.0};   // [0]=cc, [1]=dx, [2]=dy
__device__ unsigned int g_count = 0;

__global__ __launch_bounds__(NT, 2)
void fused_kernel(const float* __restrict__ I,
                  const float* __restrict__ J,
                  const float* __restrict__ S,
                  float* __restrict__ out)
{
    extern __shared__ float sm[];
    const int tid = threadIdx.x;
    const int bid = blockIdx.x;

    float acc0 = 0.f;   // cc sum (ncc blocks)
    float acc1 = 0.f;   // dx sum (smooth blocks)
    float acc2 = 0.f;   // dy sum (smooth blocks)

    if (bid < SM_BLOCKS) {
        // ---------------- smoothness: row-sliding strip ----------------
        const int strip = bid % SM_STRIPS;
        const int plane = bid / SM_STRIPS;
        const float*  spf = S + (size_t)plane * HH * WW;
        const float4* sp4 = (const float4*)spf;
        const int y0 = strip * SM_R;

        float dx = 0.f, dy = 0.f;
        float4 cur = sp4[(size_t)y0 * (WW / 4) + tid];

        #pragma unroll 4
        for (int y = y0; y < y0 + SM_R; y++) {
            float d1 = cur.y - cur.x;
            float d2 = cur.z - cur.y;
            float d3 = cur.w - cur.z;
            dx += d1 * d1 + d2 * d2 + d3 * d3;
            if (tid < (WW / 4 - 1)) {
                float nx = spf[(size_t)y * WW + 4 * tid + 4];
                float d4 = nx - cur.w;
                dx += d4 * d4;
            }
            if (y + 1 < HH) {
                float4 nxt = sp4[(size_t)(y + 1) * (WW / 4) + tid];
                float e1 = nxt.x - cur.x;
                float e2 = nxt.y - cur.y;
                float e3 = nxt.z - cur.z;
                float e4 = nxt.w - cur.w;
                dy += e1 * e1 + e2 * e2 + e3 * e3 + e4 * e4;
                cur = nxt;
            }
        }
        acc1 = dx; acc2 = dy;
    } else {
        // ---------------- NCC: fused separable 9x9 window sums ----------------
        int t = bid - SM_BLOCKS;
        const int bx = t % NCC_BX; t /= NCC_BX;
        const int by = t % NCC_BY; t /= NCC_BY;
        const float* Ib = I + (size_t)t * HH * WW;
        const float* Jb = J + (size_t)t * HH * WW;

        float* sIm = sm;
        float* sJm = sm + RGY * SX;
        float* sV0 = sm + 2 * RGY * SX;
        float* sV1 = sV0 + TSY * SX;
        float* sV2 = sV1 + TSY * SX;
        float* sV3 = sV2 + TSY * SX;
        float* sV4 = sV3 + TSY * SX;

        const int ty0 = by * TSY - 4;
        const int tx0 = bx * TSX - 4;
        const bool interior = (bx > 0) && (bx < NCC_BX - 1) && (by > 0) && (by < NCC_BY - 1);

        if (interior) {
            for (int i = tid; i < RGY * RGX; i += NT) {
                int r = i / RGX, c = i - r * RGX;
                int g = (ty0 + r) * WW + (tx0 + c);
                sIm[r * SX + c] = __ldg(Ib + g);
                sJm[r * SX + c] = __ldg(Jb + g);
            }
        } else {
            for (int i = tid; i < RGY * RGX; i += NT) {
                int r = i / RGX, c = i - r * RGX;
                int gy = ty0 + r, gx = tx0 + c;
                float vi = 0.f, vj = 0.f;
                if ((unsigned)gy < (unsigned)HH && (unsigned)gx < (unsigned)WW) {
                    int g = gy * WW + gx;
                    vi = __ldg(Ib + g);
                    vj = __ldg(Jb + g);
                }
                sIm[r * SX + c] = vi;
                sJm[r * SX + c] = vj;
            }
        }
        __syncthreads();

        // vertical sliding 9-row sums: 320 tasks (40 cols x 8 row-groups of 8)
        #pragma unroll 1
        for (int task = tid; task < RGX * (TSY / 8); task += NT) {
            const int col = task % RGX;
            const int r0  = (task / RGX) * 8;
            float aI = 0.f, aJ = 0.f, aI2 = 0.f, aJ2 = 0.f, aIJ = 0.f;
            #pragma unroll
            for (int k = 0; k < 9; k++) {
                float iv = sIm[(r0 + k) * SX + col];
                float jv = sJm[(r0 + k) * SX + col];
                aI += iv; aJ += jv;
                aI2 = fmaf(iv, iv, aI2);
                aJ2 = fmaf(jv, jv, aJ2);
                aIJ = fmaf(iv, jv, aIJ);
            }
            sV0[r0 * SX + col] = aI;
            sV1[r0 * SX + col] = aJ;
            sV2[r0 * SX + col] = aI2;
            sV3[r0 * SX + col] = aJ2;
            sV4[r0 * SX + col] = aIJ;
            #pragma unroll
            for (int o = 1; o < 8; o++) {
                const int y = r0 + o;
                float iN = sIm[(y + 8) * SX + col], jN = sJm[(y + 8) * SX + col];
                float iO = sIm[(y - 1) * SX + col], jO = sJm[(y - 1) * SX + col];
                aI += iN - iO;
                aJ += jN - jO;
                aI2 = fmaf(iN, iN, aI2); aI2 = fmaf(-iO, iO, aI2);
                aJ2 = fmaf(jN, jN, aJ2); aJ2 = fmaf(-jO, jO, aJ2);
                aIJ = fmaf(iN, jN, aIJ); aIJ = fmaf(-iO, jO, aIJ);
                sV0[y * SX + col] = aI;
                sV1[y * SX + col] = aJ;
                sV2[y * SX + col] = aI2;
                sV3[y * SX + col] = aJ2;
                sV4[y * SX + col] = aIJ;
            }
        }
        __syncthreads();

        // horizontal sliding 9-col sums: thread = (row, 8-col group); conflict-free banks
        const int row = tid >> 2;            // 0..63
        const int c0  = (tid & 3) * 8;       // 0,8,16,24
        const float* v0 = sV0 + row * SX;
        const float* v1 = sV1 + row * SX;
        const float* v2 = sV2 + row * SX;
        const float* v3 = sV3 + row * SX;
        const float* v4 = sV4 + row * SX;

        float wI = 0.f, wJ = 0.f, wI2 = 0.f, wJ2 = 0.f, wIJ = 0.f;
        #pragma unroll
        for (int k = 0; k < 9; k++) {
            wI  += v0[c0 + k];
            wJ  += v1[c0 + k];
            wI2 += v2[c0 + k];
            wJ2 += v3[c0 + k];
            wIJ += v4[c0 + k];
        }
        const float inv81 = 1.0f / 81.0f;
        float ccSum = 0.f;
        #pragma unroll
        for (int o = 0; o < 8; o++) {
            if (o) {
                const int a = c0 + o + 8, d = c0 + o - 1;
                wI  += v0[a] - v0[d];
                wJ  += v1[a] - v1[d];
                wI2 += v2[a] - v2[d];
                wJ2 += v3[a] - v3[d];
                wIJ += v4[a] - v4[d];
            }
            float cross = fmaf(-wI * inv81, wJ, wIJ);
            float Iv    = fmaf(-wI * inv81, wI, wI2);
            float Jv    = fmaf(-wJ * inv81, wJ, wJ2);
            ccSum += cross * cross * __fdividef(1.0f, fmaf(Iv, Jv, 1e-9f));
        }
        acc0 = ccSum;
        __syncthreads();   // protect sm[] reuse for reduction below
    }

    // ---------------- block reduction + global accumulate ----------------
    const unsigned full = 0xffffffffu;
    #pragma unroll
    for (int off = 16; off; off >>= 1) {
        acc0 += __shfl_down_sync(full, acc0, off);
        acc1 += __shfl_down_sync(full, acc1, off);
        acc2 += __shfl_down_sync(full, acc2, off);
    }
    if ((tid & 31) == 0) {
        const int w = tid >> 5;
        sm[w]      = acc0;
        sm[8 + w]  = acc1;
        sm[16 + w] = acc2;
    }
    __syncthreads();
    if (tid == 0) {
        float a0 = 0.f, a1 = 0.f, a2 = 0.f;
        #pragma unroll
        for (int w = 0; w < NT / 32; w++) {
            a0 += sm[w]; a1 += sm[8 + w]; a2 += sm[16 + w];
        }
        if (bid < SM_BLOCKS) {
            atomicAdd(&g_acc[1], (double)a1);
            atomicAdd(&g_acc[2], (double)a2);
        } else {
            atomicAdd(&g_acc[0], (double)a0);
        }
        __threadfence();
        unsigned old = atomicAdd(&g_count, 1u);
        if (old == TOTAL_BLOCKS - 1) {
            __threadfence();
            volatile double* ga = g_acc;
            double c  = ga[0];
            double xs = ga[1];
            double ys = ga[2];
            double nccl = -c / ((double)BB * HH * WW);
            double mdx  = xs / ((double)BB * 2.0 * HH * (WW - 1));
            double mdy  = ys / ((double)BB * 2.0 * (HH - 1) * WW);
            double sml  = (mdx + mdy) * 0.5 * 0.01;
            out[0] = (float)(nccl + sml);
            out[1] = (float)nccl;
            out[2] = (float)sml;
            // reset for the next graph replay
            ga[0] = 0.0; ga[1] = 0.0; ga[2] = 0.0;
            __threadfence();
            atomicExch(&g_count, 0u);
        }
    }
}

extern "C" void kernel_launch(void* const* d_in, const int* in_sizes, int n_in,
                              void* d_out, int out_size)
{
    const float* I = (const float*)d_in[0];
    const float* J = (const float*)d_in[1];
    const float* s = (const float*)d_in[2];
    // d_in[3] = sum_filt (all-ones 9x9) is baked into the math
    float* out = (float*)d_out;

    const size_t smem = SMEM_FLOATS * sizeof(float);
    cudaFuncSetAttribute(fused_kernel, cudaFuncAttributeMaxDynamicSharedMemorySize, (int)smem);
    fused_kernel<<<TOTAL_BLOCKS, NT, smem>>>(I, J, s, out);
}

// round 3
// speedup vs baseline: 1.9001x; 1.7737x over previous
#include <cuda_runtime.h>

#define BB 8
#define HH 1024
#define WW 1024
#define NT 256

// ---- NCC warp-task decomposition ----
#define OUTW 24                       // output cols per warp (lanes 0..23)
#define NSTRIP 43                     // ceil(1024/24)
#define SEG 64                        // output rows per warp task
#define VSEG (HH / SEG)               // 16
#define NCC_WTASKS (NSTRIP * VSEG * BB)   // 5504
#define NCC_BLOCKS (NCC_WTASKS / 8)       // 688  (8 warps/block)

// ---- smoothness strips ----
#define SM_R 64
#define SM_STRIPS (HH / SM_R)             // 16
#define SM_PLANES (BB * 2)                // 16
#define SM_BLOCKS (SM_PLANES * SM_STRIPS) // 256

#define TOTAL_BLOCKS (SM_BLOCKS + NCC_BLOCKS)  // 944

__device__ double g_acc[3] = {0.0, 0.0, 0.0};   // [0]=cc, [1]=dx, [2]=dy
__device__ unsigned int g_count = 0;

__device__ __forceinline__ float tree9(float a) {
    // returns sum over lanes l..l+8 of a (valid for l <= 23)
    float b = a + __shfl_down_sync(0xffffffffu, a, 1);
    float c = b + __shfl_down_sync(0xffffffffu, b, 2);
    float d = c + __shfl_down_sync(0xffffffffu, c, 4);
    return d + __shfl_down_sync(0xffffffffu, a, 8);
}

__global__ __launch_bounds__(NT)
void fused_kernel(const float* __restrict__ I,
                  const float* __restrict__ J,
                  const float* __restrict__ S,
                  float* __restrict__ out)
{
    __shared__ float red[3][NT / 32];
    const int tid  = threadIdx.x;
    const int bid  = blockIdx.x;
    const int lane = tid & 31;

    float acc0 = 0.f, acc1 = 0.f, acc2 = 0.f;

    if (bid < SM_BLOCKS) {
        // ---------------- smoothness: row-sliding strip (HBM-bound) ----------------
        const int strip = bid % SM_STRIPS;
        const int plane = bid / SM_STRIPS;
        const float*  spf = S + (size_t)plane * HH * WW;
        const float4* sp4 = (const float4*)spf;
        const int y0 = strip * SM_R;

        float dx = 0.f, dy = 0.f;
        float4 cur = sp4[(size_t)y0 * (WW / 4) + tid];

        #pragma unroll 4
        for (int y = y0; y < y0 + SM_R; y++) {
            float d1 = cur.y - cur.x;
            float d2 = cur.z - cur.y;
            float d3 = cur.w - cur.z;
            dx += d1 * d1 + d2 * d2 + d3 * d3;
            if (tid < (WW / 4 - 1)) {
                float nx = spf[(size_t)y * WW + 4 * tid + 4];
                float d4 = nx - cur.w;
                dx += d4 * d4;
            }
            if (y + 1 < HH) {
                float4 nxt = sp4[(size_t)(y + 1) * (WW / 4) + tid];
                float e1 = nxt.x - cur.x;
                float e2 = nxt.y - cur.y;
                float e3 = nxt.z - cur.z;
                float e4 = nxt.w - cur.w;
                dy += e1 * e1 + e2 * e2 + e3 * e3 + e4 * e4;
                cur = nxt;
            }
        }
        acc1 = dx; acc2 = dy;
    } else {
        // ---------------- NCC: register vertical slide + shuffle-tree horizontal ----
        const int w = (bid - SM_BLOCKS) * 8 + (tid >> 5);
        const int s = w % NSTRIP;
        const int r = w / NSTRIP;
        const int v = r % VSEG;
        const int b = r / VSEG;

        const int xr = s * OUTW + lane - 4;               // raw column for this lane
        const bool colok = (unsigned)xr < (unsigned)WW;
        const int xc = colok ? xr : 0;
        const float* Ib = I + (size_t)b * HH * WW + xc;
        const float* Jb = J + (size_t)b * HH * WW + xc;

        const int y0 = v * SEG;
        const bool outok = (lane < OUTW) && (s * OUTW + lane < WW);

        // prefill running sums with rows y0-4 .. y0+3
        float sIv = 0.f, sJv = 0.f, sII = 0.f, sJJ = 0.f, sIJ = 0.f;
        #pragma unroll
        for (int k = -4; k < 4; k++) {
            int y = y0 + k;
            bool ok = colok && ((unsigned)y < (unsigned)HH);
            float iv = ok ? __ldg(Ib + y * WW) : 0.f;
            float jv = ok ? __ldg(Jb + y * WW) : 0.f;
            sIv += iv; sJv += jv;
            sII = fmaf(iv, iv, sII);
            sJJ = fmaf(jv, jv, sJJ);
            sIJ = fmaf(iv, jv, sIJ);
        }

        const float inv81 = 1.0f / 81.0f;
        float ccSum = 0.f;

        #pragma unroll 2
        for (int y = y0; y < y0 + SEG; y++) {
            const int yn = y + 4;
            const int yo = y - 4;
            const bool okn = colok && (yn < HH);
            const bool oko = colok && (yo >= 0);

            float iN = okn ? __ldg(Ib + yn * WW) : 0.f;
            float jN = okn ? __ldg(Jb + yn * WW) : 0.f;
            float iO = oko ? __ldg(Ib + yo * WW) : 0.f;
            float jO = oko ? __ldg(Jb + yo * WW) : 0.f;

            sIv += iN; sJv += jN;
            sII = fmaf(iN, iN, sII);
            sJJ = fmaf(jN, jN, sJJ);
            sIJ = fmaf(iN, jN, sIJ);

            // horizontal 9-tap window sums (lanes 0..23 valid)
            float TI  = tree9(sIv);
            float TJ  = tree9(sJv);
            float TII = tree9(sII);
            float TJJ = tree9(sJJ);
            float TIJ = tree9(sIJ);

            float cross = fmaf(-TI * inv81, TJ, TIJ);
            float Iv    = fmaf(-TI * inv81, TI, TII);
            float Jv    = fmaf(-TJ * inv81, TJ, TJJ);
            float cc    = cross * cross * __fdividef(1.0f, fmaf(Iv, Jv, 1e-9f));
            if (outok) ccSum += cc;

            // slide: drop row y-4
            sIv -= iO; sJv -= jO;
            sII = fmaf(-iO, iO, sII);
            sJJ = fmaf(-jO, jO, sJJ);
            sIJ = fmaf(-iO, jO, sIJ);
        }
        acc0 = ccSum;
    }

    // ---------------- block reduction + global accumulate ----------------
    const unsigned full = 0xffffffffu;
    #pragma unroll
    for (int off = 16; off; off >>= 1) {
        acc0 += __shfl_down_sync(full, acc0, off);
        acc1 += __shfl_down_sync(full, acc1, off);
        acc2 += __shfl_down_sync(full, acc2, off);
    }
    if (lane == 0) {
        const int wi = tid >> 5;
        red[0][wi] = acc0;
        red[1][wi] = acc1;
        red[2][wi] = acc2;
    }
    __syncthreads();
    if (tid == 0) {
        float a0 = 0.f, a1 = 0.f, a2 = 0.f;
        #pragma unroll
        for (int wi = 0; wi < NT / 32; wi++) {
            a0 += red[0][wi]; a1 += red[1][wi]; a2 += red[2][wi];
        }
        if (bid < SM_BLOCKS) {
            atomicAdd(&g_acc[1], (double)a1);
            atomicAdd(&g_acc[2], (double)a2);
        } else {
            atomicAdd(&g_acc[0], (double)a0);
        }
        __threadfence();
        unsigned old = atomicAdd(&g_count, 1u);
        if (old == TOTAL_BLOCKS - 1) {
            __threadfence();
            volatile double* ga = g_acc;
            double c  = ga[0];
            double xs = ga[1];
            double ys = ga[2];
            double nccl = -c / ((double)BB * HH * WW);
            double mdx  = xs / ((double)BB * 2.0 * HH * (WW - 1));
            double mdy  = ys / ((double)BB * 2.0 * (HH - 1) * WW);
            double sml  = (mdx + mdy) * 0.5 * 0.01;
            out[0] = (float)(nccl + sml);
            out[1] = (float)nccl;
            out[2] = (float)sml;
            // reset for next graph replay
            ga[0] = 0.0; ga[1] = 0.0; ga[2] = 0.0;
            __threadfence();
            atomicExch(&g_count, 0u);
        }
    }
}

extern "C" void kernel_launch(void* const* d_in, const int* in_sizes, int n_in,
                              void* d_out, int out_size)
{
    const float* I = (const float*)d_in[0];
    const float* J = (const float*)d_in[1];
    const float* s = (const float*)d_in[2];
    // d_in[3] = sum_filt (all-ones 9x9) is baked into the math
    float* out = (float*)d_out;

    fused_kernel<<<TOTAL_BLOCKS, NT>>>(I, J, s, out);
}

// round 4
// speedup vs baseline: 2.3425x; 1.2328x over previous
#include <cuda_runtime.h>

#define BB 8
#define HH 1024
#define WW 1024
#define NT 256

// ---- NCC: float2-per-lane warp tasks ----
#define OUTW 56                        // output cols per warp-row
#define NSTRIP 19                      // ceil(1024/56)
#define SEG 32                         // output rows per warp task
#define VSEG (HH / SEG)                // 32
#define NCC_WT (NSTRIP * VSEG * BB)    // 4864
#define NCC_BLOCKS (NCC_WT / 8)        // 608

// ---- smoothness strips ----
#define SM_R 64
#define SM_STRIPS (HH / SM_R)             // 16
#define SM_PLANES (BB * 2)                // 16
#define SM_BLOCKS (SM_PLANES * SM_STRIPS) // 256

#define TOTAL_BLOCKS (NCC_BLOCKS + SM_BLOCKS)  // 864

__device__ double g_acc[3] = {0.0, 0.0, 0.0};   // [0]=cc, [1]=dx, [2]=dy
__device__ unsigned int g_count = 0;

// Horizontal 9-tap window sums for a lane owning cols (a, b) = (ca, ca+1).
// wA = sum cols ca-4..ca+4 ; wB = sum cols ca-3..ca+5. Valid for lanes 2..29.
__device__ __forceinline__ void hwin(float va, float vb, float& wA, float& wB) {
    const unsigned m = 0xffffffffu;
    float P   = va + vb;                             // pair l
    float t1  = P + __shfl_down_sync(m, P, 1);       // pairs l,l+1
    float Q   = t1 + __shfl_down_sync(m, t1, 2);     // pairs l..l+3
    float Qm2 = __shfl_up_sync(m, Q, 2);             // pairs l-2..l+1 = ca-4..ca+3
    float Qm1 = __shfl_up_sync(m, Q, 1);             // pairs l-1..l+2 = ca-2..ca+5
    float ap2 = __shfl_down_sync(m, va, 2);          // col ca+4
    float bm2 = __shfl_up_sync(m, vb, 2);            // col ca-3
    wA = Qm2 + ap2;
    wB = Qm1 + bm2;
}

template<bool MASKED>
__device__ __forceinline__ float ncc_task(const float2* __restrict__ Ip,
                                          const float2* __restrict__ Jp,
                                          int y0, bool okA, bool okB,
                                          bool maskA, bool maskB)
{
    const int RS = WW / 2;
    const float2 z = make_float2(0.f, 0.f);

    float sIa=0,sIb=0,sJa=0,sJb=0,sIIa=0,sIIb=0,sJJa=0,sJJb=0,sIJa=0,sIJb=0;

    // prefill rows y0-4 .. y0+3
    {
        const float2* pI = Ip + (long)(y0 - 4) * RS;
        const float2* pJ = Jp + (long)(y0 - 4) * RS;
        #pragma unroll
        for (int k = 0; k < 8; k++) {
            bool okr = (y0 - 4 + k) >= 0;
            float2 vi = okr ? pI[0] : z;
            float2 vj = okr ? pJ[0] : z;
            if (MASKED) {
                if (!okA) { vi.x = 0.f; vj.x = 0.f; }
                if (!okB) { vi.y = 0.f; vj.y = 0.f; }
            }
            sIa += vi.x; sIb += vi.y; sJa += vj.x; sJb += vj.y;
            sIIa = fmaf(vi.x, vi.x, sIIa); sIIb = fmaf(vi.y, vi.y, sIIb);
            sJJa = fmaf(vj.x, vj.x, sJJa); sJJb = fmaf(vj.y, vj.y, sJJb);
            sIJa = fmaf(vi.x, vj.x, sIJa); sIJb = fmaf(vi.y, vj.y, sIJb);
            pI += RS; pJ += RS;
        }
    }

    const float2* pIn = Ip + (long)(y0 + 4) * RS;
    const float2* pJn = Jp + (long)(y0 + 4) * RS;
    const float2* pIo = Ip + (long)(y0 - 4) * RS;
    const float2* pJo = Jp + (long)(y0 - 4) * RS;

    const float inv81 = 1.0f / 81.0f;
    float ccSum = 0.f;

    #pragma unroll 2
    for (int y = y0; y < y0 + SEG; y++) {
        const bool okn = (y + 4) < HH;
        const bool oko = (y - 4) >= 0;
        float2 iN = okn ? pIn[0] : z;
        float2 jN = okn ? pJn[0] : z;
        float2 iO = oko ? pIo[0] : z;
        float2 jO = oko ? pJo[0] : z;
        pIn += RS; pJn += RS; pIo += RS; pJo += RS;
        if (MASKED) {
            if (!okA) { iN.x = 0.f; jN.x = 0.f; iO.x = 0.f; jO.x = 0.f; }
            if (!okB) { iN.y = 0.f; jN.y = 0.f; iO.y = 0.f; jO.y = 0.f; }
        }

        // add row y+4
        sIa += iN.x; sIb += iN.y; sJa += jN.x; sJb += jN.y;
        sIIa = fmaf(iN.x, iN.x, sIIa); sIIb = fmaf(iN.y, iN.y, sIIb);
        sJJa = fmaf(jN.x, jN.x, sJJa); sJJb = fmaf(jN.y, jN.y, sJJb);
        sIJa = fmaf(iN.x, jN.x, sIJa); sIJb = fmaf(iN.y, jN.y, sIJb);

        // horizontal 9-tap on the 5 vertical sums
        float TIa,TIb,TJa,TJb,TIIa,TIIb,TJJa,TJJb,TIJa,TIJb;
        hwin(sIa,  sIb,  TIa,  TIb);
        hwin(sJa,  sJb,  TJa,  TJb);
        hwin(sIIa, sIIb, TIIa, TIIb);
        hwin(sJJa, sJJb, TJJa, TJJb);
        hwin(sIJa, sIJb, TIJa, TIJb);

        // col A
        {
            float u  = TIa * inv81;
            float cr = fmaf(-u, TJa, TIJa);
            float iv = fmaf(-u, TIa, TIIa);
            float jv = fmaf(-TJa * inv81, TJa, TJJa);
            float cc = cr * cr * __fdividef(1.0f, fmaf(iv, jv, 1e-9f));
            if (maskA) ccSum += cc;
        }
        // col B
        {
            float u  = TIb * inv81;
            float cr = fmaf(-u, TJb, TIJb);
            float iv = fmaf(-u, TIb, TIIb);
            float jv = fmaf(-TJb * inv81, TJb, TJJb);
            float cc = cr * cr * __fdividef(1.0f, fmaf(iv, jv, 1e-9f));
            if (maskB) ccSum += cc;
        }

        // drop row y-4
        sIa -= iO.x; sIb -= iO.y; sJa -= jO.x; sJb -= jO.y;
        sIIa = fmaf(-iO.x, iO.x, sIIa); sIIb = fmaf(-iO.y, iO.y, sIIb);
        sJJa = fmaf(-jO.x, jO.x, sJJa); sJJb = fmaf(-jO.y, jO.y, sJJb);
        sIJa = fmaf(-iO.x, jO.x, sIJa); sIJb = fmaf(-iO.y, jO.y, sIJb);
    }
    return ccSum;
}

__global__ __launch_bounds__(NT)
void fused_kernel(const float* __restrict__ I,
                  const float* __restrict__ J,
                  const float* __restrict__ S,
                  float* __restrict__ out)
{
    __shared__ float red[3][NT / 32];
    const int tid  = threadIdx.x;
    const int bid  = blockIdx.x;
    const int lane = tid & 31;

    float acc0 = 0.f, acc1 = 0.f, acc2 = 0.f;

    if (bid < NCC_BLOCKS) {
        // ---------------- NCC ----------------
        const int w = bid * 8 + (tid >> 5);
        const int s = w % NSTRIP;
        const int r = w / NSTRIP;
        const int v = r % VSEG;
        const int b = r / VSEG;

        const int ca = s * OUTW - 4 + 2 * lane;         // even
        const bool okA = (unsigned)ca < (unsigned)WW;
        const bool okB = (unsigned)(ca + 1) < (unsigned)WW;
        int cac = ca < 0 ? 0 : (ca > (WW - 2) ? (WW - 2) : ca);

        const float2* Ip = (const float2*)(I + (size_t)b * HH * WW + cac);
        const float2* Jp = (const float2*)(J + (size_t)b * HH * WW + cac);

        const bool lmid  = (lane >= 2) && (lane <= 29);
        const bool maskA = lmid && okA;
        const bool maskB = lmid && okB;
        const int  y0    = v * SEG;

        const bool clean = __all_sync(0xffffffffu, okA && okB);
        acc0 = clean ? ncc_task<false>(Ip, Jp, y0, okA, okB, maskA, maskB)
                     : ncc_task<true >(Ip, Jp, y0, okA, okB, maskA, maskB);
    } else {
        // ---------------- smoothness: row-sliding strip ----------------
        const int sbid  = bid - NCC_BLOCKS;
        const int strip = sbid % SM_STRIPS;
        const int plane = sbid / SM_STRIPS;
        const float*  spf = S + (size_t)plane * HH * WW;
        const float4* sp4 = (const float4*)spf;
        const int y0 = strip * SM_R;

        float dx = 0.f, dy = 0.f;
        float4 cur = sp4[(size_t)y0 * (WW / 4) + tid];

        #pragma unroll 4
        for (int y = y0; y < y0 + SM_R; y++) {
            float d1 = cur.y - cur.x;
            float d2 = cur.z - cur.y;
            float d3 = cur.w - cur.z;
            dx += d1 * d1 + d2 * d2 + d3 * d3;
            if (tid < (WW / 4 - 1)) {
                float nx = spf[(size_t)y * WW + 4 * tid + 4];
                float d4 = nx - cur.w;
                dx += d4 * d4;
            }
            if (y + 1 < HH) {
                float4 nxt = sp4[(size_t)(y + 1) * (WW / 4) + tid];
                float e1 = nxt.x - cur.x;
                float e2 = nxt.y - cur.y;
                float e3 = nxt.z - cur.z;
                float e4 = nxt.w - cur.w;
                dy += e1 * e1 + e2 * e2 + e3 * e3 + e4 * e4;
                cur = nxt;
            }
        }
        acc1 = dx; acc2 = dy;
    }

    // ---------------- block reduction + global accumulate ----------------
    const unsigned full = 0xffffffffu;
    #pragma unroll
    for (int off = 16; off; off >>= 1) {
        acc0 += __shfl_down_sync(full, acc0, off);
        acc1 += __shfl_down_sync(full, acc1, off);
        acc2 += __shfl_down_sync(full, acc2, off);
    }
    if (lane == 0) {
        const int wi = tid >> 5;
        red[0][wi] = acc0;
        red[1][wi] = acc1;
        red[2][wi] = acc2;
    }
    __syncthreads();
    if (tid == 0) {
        float a0 = 0.f, a1 = 0.f, a2 = 0.f;
        #pragma unroll
        for (int wi = 0; wi < NT / 32; wi++) {
            a0 += red[0][wi]; a1 += red[1][wi]; a2 += red[2][wi];
        }
        if (bid < NCC_BLOCKS) {
            atomicAdd(&g_acc[0], (double)a0);
        } else {
            atomicAdd(&g_acc[1], (double)a1);
            atomicAdd(&g_acc[2], (double)a2);
        }
        __threadfence();
        unsigned old = atomicAdd(&g_count, 1u);
        if (old == TOTAL_BLOCKS - 1) {
            __threadfence();
            volatile double* ga = g_acc;
            double c  = ga[0];
            double xs = ga[1];
            double ys = ga[2];
            double nccl = -c / ((double)BB * HH * WW);
            double mdx  = xs / ((double)BB * 2.0 * HH * (WW - 1));
            double mdy  = ys / ((double)BB * 2.0 * (HH - 1) * WW);
            double sml  = (mdx + mdy) * 0.5 * 0.01;
            out[0] = (float)(nccl + sml);
            out[1] = (float)nccl;
            out[2] = (float)sml;
            // reset for next graph replay
            ga[0] = 0.0; ga[1] = 0.0; ga[2] = 0.0;
            __threadfence();
            atomicExch(&g_count, 0u);
        }
    }
}

extern "C" void kernel_launch(void* const* d_in, const int* in_sizes, int n_in,
                              void* d_out, int out_size)
{
    const float* I = (const float*)d_in[0];
    const float* J = (const float*)d_in[1];
    const float* s = (const float*)d_in[2];
    // d_in[3] = sum_filt (all-ones 9x9) is baked into the math
    float* out = (float*)d_out;

    fused_kernel<<<TOTAL_BLOCKS, NT>>>(I, J, s, out);
}